// round 4
// baseline (speedup 1.0000x reference)
#include <cuda_runtime.h>
#include <cstdint>

// Problem shape: predicted/target are [B=2, C=26, 96,96,96] fp32.
#define BB 2
#define CC 26
#define NVOX (96*96*96)       // 884736 voxels per (batch, channel)
#define N4   (NVOX/4)         // 221184 float4 per (batch, channel)
#define THREADS 256
#define BLOCKS_X (N4/THREADS) // 864, exact
#define NBLOCKS (BLOCKS_X*BB) // 1728

// Device scratch (zero-initialized at module load; the finalizing block resets
// them after reading, so every call/graph-replay starts from zeros).
__device__ int g_total[BB*CC];
__device__ int g_correct[BB*CC];
__device__ unsigned int g_arrive;

__global__ void __launch_bounds__(THREADS)
idr_fused_kernel(const float* __restrict__ pred, const float* __restrict__ targ,
                 float* __restrict__ out) {
    __shared__ int s_total[CC];
    __shared__ int s_corr[CC];
    const int tid = threadIdx.x;
    if (tid < CC) { s_total[tid] = 0; s_corr[tid] = 0; }
    __syncthreads();

    const int b = blockIdx.y;
    const size_t i = (size_t)blockIdx.x * THREADS + tid;   // float4 index within channel
    const float4* __restrict__ p = (const float4*)pred + (size_t)b * CC * N4 + i;
    const float4* __restrict__ t = (const float4*)targ + (size_t)b * CC * N4 + i;

    // argmax over channels, predicted (first-max tie-break: strict >)
    float4 pm = __ldcs(p);
    int pax = 0, pay = 0, paz = 0, paw = 0;
    #pragma unroll
    for (int c = 1; c < CC; c++) {
        float4 v = __ldcs(p + (size_t)c * N4);
        if (v.x > pm.x) { pm.x = v.x; pax = c; }
        if (v.y > pm.y) { pm.y = v.y; pay = c; }
        if (v.z > pm.z) { pm.z = v.z; paz = c; }
        if (v.w > pm.w) { pm.w = v.w; paw = c; }
    }

    // argmax over channels, target
    float4 tm = __ldcs(t);
    int tax = 0, tay = 0, taz = 0, taw = 0;
    #pragma unroll
    for (int c = 1; c < CC; c++) {
        float4 v = __ldcs(t + (size_t)c * N4);
        if (v.x > tm.x) { tm.x = v.x; tax = c; }
        if (v.y > tm.y) { tm.y = v.y; tay = c; }
        if (v.z > tm.z) { tm.z = v.z; taz = c; }
        if (v.w > tm.w) { tm.w = v.w; taw = c; }
    }

    // block-local histogram by target class; correct = (pred label == target label)
    atomicAdd(&s_total[tax], 1); if (pax == tax) atomicAdd(&s_corr[tax], 1);
    atomicAdd(&s_total[tay], 1); if (pay == tay) atomicAdd(&s_corr[tay], 1);
    atomicAdd(&s_total[taz], 1); if (paz == taz) atomicAdd(&s_corr[taz], 1);
    atomicAdd(&s_total[taw], 1); if (paw == taw) atomicAdd(&s_corr[taw], 1);

    __syncthreads();
    if (tid < CC) {
        if (s_total[tid]) atomicAdd(&g_total[b*CC + tid], s_total[tid]);
        if (s_corr[tid])  atomicAdd(&g_correct[b*CC + tid], s_corr[tid]);
    }

    // Last-block-done finalize + reset. No block ever waits on another:
    // the arrival ticket is fire-and-forget, so this cannot deadlock
    // regardless of residency/scheduling.
    __syncthreads();
    if (tid == 0) {
        __threadfence();                                   // publish this block's adds
        unsigned int ticket = atomicAdd(&g_arrive, 1u);
        if (ticket == (unsigned int)(NBLOCKS - 1)) {       // all prior adds now visible
            __threadfence();                               // acquire side
            float acc = 0.0f;
            int n_valid = 0;
            #pragma unroll
            for (int bb = 0; bb < BB; bb++) {
                float sum = 0.0f;
                int np = 0;
                #pragma unroll
                for (int c = 1; c < CC; c++) {             // class 0 excluded
                    int tot = g_total[bb*CC + c];
                    if (tot > 0) {
                        np++;
                        sum += (float)g_correct[bb*CC + c] / (float)tot;
                    }
                }
                if (np > 0) { n_valid++; acc += sum / (float)np; }
            }
            out[0] = (n_valid > 0) ? acc / (float)n_valid : 0.0f;
            // reset for next call / graph replay
            #pragma unroll
            for (int k = 0; k < BB*CC; k++) { g_total[k] = 0; g_correct[k] = 0; }
            g_arrive = 0u;
            __threadfence();
        }
    }
}

extern "C" void kernel_launch(void* const* d_in, const int* in_sizes, int n_in,
                              void* d_out, int out_size) {
    const float* pred = (const float*)d_in[0];
    const float* targ = (const float*)d_in[1];
    float* out = (float*)d_out;

    dim3 grid(BLOCKS_X, BB);
    idr_fused_kernel<<<grid, THREADS>>>(pred, targ, out);
}

// round 5
// speedup vs baseline: 1.0360x; 1.0360x over previous
#include <cuda_runtime.h>
#include <cstdint>

// Problem shape: predicted/target are [B=2, C=26, 96,96,96] fp32.
#define BB 2
#define CC 26
#define NVOX (96*96*96)       // 884736 voxels per (batch, channel)
#define N4   (NVOX/4)         // 221184 float4 per (batch, channel)
#define THREADS 256
#define BLOCKS_X (N4/THREADS) // 864, exact
#define NBLOCKS (BLOCKS_X*BB) // 1728

// Device scratch (zero-initialized at module load; the finalizing block resets
// them after reading, so every call/graph-replay starts from zeros).
__device__ int g_total[BB*CC];
__device__ int g_correct[BB*CC];
__device__ unsigned int g_arrive;

__global__ void __launch_bounds__(THREADS)
idr_fused_kernel(const float* __restrict__ pred, const float* __restrict__ targ,
                 float* __restrict__ out) {
    __shared__ int s_total[CC];
    __shared__ int s_corr[CC];
    const int tid = threadIdx.x;
    if (tid < CC) { s_total[tid] = 0; s_corr[tid] = 0; }
    __syncthreads();

    const int b = blockIdx.y;
    const size_t i = (size_t)blockIdx.x * THREADS + tid;   // float4 index within channel
    const float4* __restrict__ p = (const float4*)pred + (size_t)b * CC * N4;
    const float4* __restrict__ t = (const float4*)targ + (size_t)b * CC * N4;

    // ===== R2 loop body, verbatim (plain loads, unroll 5 → moderate MLP, low regs) =====
    // argmax over channels for predicted (first-max tie-break: strict >)
    float4 pm = p[i];
    int pax = 0, pay = 0, paz = 0, paw = 0;
    #pragma unroll 5
    for (int c = 1; c < CC; c++) {
        float4 v = p[(size_t)c * N4 + i];
        if (v.x > pm.x) { pm.x = v.x; pax = c; }
        if (v.y > pm.y) { pm.y = v.y; pay = c; }
        if (v.z > pm.z) { pm.z = v.z; paz = c; }
        if (v.w > pm.w) { pm.w = v.w; paw = c; }
    }

    // argmax over channels for target
    float4 tm = t[i];
    int tax = 0, tay = 0, taz = 0, taw = 0;
    #pragma unroll 5
    for (int c = 1; c < CC; c++) {
        float4 v = t[(size_t)c * N4 + i];
        if (v.x > tm.x) { tm.x = v.x; tax = c; }
        if (v.y > tm.y) { tm.y = v.y; tay = c; }
        if (v.z > tm.z) { tm.z = v.z; taz = c; }
        if (v.w > tm.w) { tm.w = v.w; taw = c; }
    }

    // block-local histogram by target class; correct = (pred label == target label)
    atomicAdd(&s_total[tax], 1); if (pax == tax) atomicAdd(&s_corr[tax], 1);
    atomicAdd(&s_total[tay], 1); if (pay == tay) atomicAdd(&s_corr[tay], 1);
    atomicAdd(&s_total[taz], 1); if (paz == taz) atomicAdd(&s_corr[taz], 1);
    atomicAdd(&s_total[taw], 1); if (paw == taw) atomicAdd(&s_corr[taw], 1);

    __syncthreads();
    if (tid < CC) {
        if (s_total[tid]) atomicAdd(&g_total[b*CC + tid], s_total[tid]);
        if (s_corr[tid])  atomicAdd(&g_correct[b*CC + tid], s_corr[tid]);
    }

    // Last-block-done finalize + reset (fire-and-forget ticket; no block waits).
    __syncthreads();
    if (tid == 0) {
        __threadfence();                                   // publish this block's adds
        unsigned int ticket = atomicAdd(&g_arrive, 1u);
        if (ticket == (unsigned int)(NBLOCKS - 1)) {       // all prior adds now visible
            __threadfence();                               // acquire side
            float acc = 0.0f;
            int n_valid = 0;
            #pragma unroll
            for (int bb = 0; bb < BB; bb++) {
                float sum = 0.0f;
                int np = 0;
                #pragma unroll
                for (int c = 1; c < CC; c++) {             // class 0 excluded
                    int tot = g_total[bb*CC + c];
                    if (tot > 0) {
                        np++;
                        sum += (float)g_correct[bb*CC + c] / (float)tot;
                    }
                }
                if (np > 0) { n_valid++; acc += sum / (float)np; }
            }
            out[0] = (n_valid > 0) ? acc / (float)n_valid : 0.0f;
            // reset for next call / graph replay
            #pragma unroll
            for (int k = 0; k < BB*CC; k++) { g_total[k] = 0; g_correct[k] = 0; }
            g_arrive = 0u;
            __threadfence();
        }
    }
}

extern "C" void kernel_launch(void* const* d_in, const int* in_sizes, int n_in,
                              void* d_out, int out_size) {
    const float* pred = (const float*)d_in[0];
    const float* targ = (const float*)d_in[1];
    float* out = (float*)d_out;

    dim3 grid(BLOCKS_X, BB);
    idr_fused_kernel<<<grid, THREADS>>>(pred, targ, out);
}

// round 7
// speedup vs baseline: 1.1176x; 1.0788x over previous
#include <cuda_runtime.h>
#include <cstdint>

// Problem shape: predicted/target are [B=2, C=26, 96,96,96] fp32.
#define BB 2
#define CC 26
#define NVOX (96*96*96)       // 884736 voxels per (batch, channel)
#define N4   (NVOX/4)         // 221184 float4 per (batch, channel)
#define THREADS 256
#define BLOCKS_X (N4/THREADS) // 864, exact

// Device scratch (zero-initialized at module load; finalize kernel resets them
// after reading, so every call/graph-replay starts from zeros).
__device__ int g_total[BB*CC];
__device__ int g_correct[BB*CC];

__global__ void __launch_bounds__(THREADS)
idr_hist_kernel(const float* __restrict__ pred, const float* __restrict__ targ) {
    __shared__ int s_total[CC];
    __shared__ int s_corr[CC];
    const int tid = threadIdx.x;
    if (tid < CC) { s_total[tid] = 0; s_corr[tid] = 0; }
    __syncthreads();

    const int b = blockIdx.y;
    const size_t i = (size_t)blockIdx.x * THREADS + tid;   // float4 index within channel
    const float4* __restrict__ p = (const float4*)pred + (size_t)b * CC * N4;
    const float4* __restrict__ t = (const float4*)targ + (size_t)b * CC * N4;

    // argmax over channels for predicted (first-max tie-break: strict >)
    float4 pm = p[i];
    int pax = 0, pay = 0, paz = 0, paw = 0;
    #pragma unroll 5
    for (int c = 1; c < CC; c++) {
        float4 v = p[(size_t)c * N4 + i];
        if (v.x > pm.x) { pm.x = v.x; pax = c; }
        if (v.y > pm.y) { pm.y = v.y; pay = c; }
        if (v.z > pm.z) { pm.z = v.z; paz = c; }
        if (v.w > pm.w) { pm.w = v.w; paw = c; }
    }

    // argmax over channels for target
    float4 tm = t[i];
    int tax = 0, tay = 0, taz = 0, taw = 0;
    #pragma unroll 5
    for (int c = 1; c < CC; c++) {
        float4 v = t[(size_t)c * N4 + i];
        if (v.x > tm.x) { tm.x = v.x; tax = c; }
        if (v.y > tm.y) { tm.y = v.y; tay = c; }
        if (v.z > tm.z) { tm.z = v.z; taz = c; }
        if (v.w > tm.w) { tm.w = v.w; taw = c; }
    }

    // block-local histogram by target class; correct = (pred label == target label)
    atomicAdd(&s_total[tax], 1); if (pax == tax) atomicAdd(&s_corr[tax], 1);
    atomicAdd(&s_total[tay], 1); if (pay == tay) atomicAdd(&s_corr[tay], 1);
    atomicAdd(&s_total[taz], 1); if (paz == taz) atomicAdd(&s_corr[taz], 1);
    atomicAdd(&s_total[taw], 1); if (paw == taw) atomicAdd(&s_corr[taw], 1);

    __syncthreads();
    if (tid < CC) {
        if (s_total[tid]) atomicAdd(&g_total[b*CC + tid], s_total[tid]);
        if (s_corr[tid])  atomicAdd(&g_correct[b*CC + tid], s_corr[tid]);
    }
    // NO epilogue: no extra sync, no fence, no ticket. Blocks retire immediately.
}

// Finalize: compute output from the [2,26] histograms, then reset them so the
// next graph replay starts from zeros (absorbs the old zero kernel).
__global__ void idr_finalize_kernel(float* __restrict__ out) {
    if (threadIdx.x != 0 || blockIdx.x != 0) return;
    float acc = 0.0f;
    int n_valid = 0;
    #pragma unroll
    for (int bb = 0; bb < BB; bb++) {
        float sum = 0.0f;
        int np = 0;
        #pragma unroll
        for (int c = 1; c < CC; c++) {       // class 0 (background) excluded
            int tot = g_total[bb*CC + c];
            if (tot > 0) {
                np++;
                sum += (float)g_correct[bb*CC + c] / (float)tot;
            }
        }
        if (np > 0) { n_valid++; acc += sum / (float)np; }
    }
    out[0] = (n_valid > 0) ? acc / (float)n_valid : 0.0f;
    #pragma unroll
    for (int k = 0; k < BB*CC; k++) { g_total[k] = 0; g_correct[k] = 0; }
}

extern "C" void kernel_launch(void* const* d_in, const int* in_sizes, int n_in,
                              void* d_out, int out_size) {
    const float* pred = (const float*)d_in[0];
    const float* targ = (const float*)d_in[1];
    float* out = (float*)d_out;

    dim3 grid(BLOCKS_X, BB);
    idr_hist_kernel<<<grid, THREADS>>>(pred, targ);
    idr_finalize_kernel<<<1, 32>>>(out);
}

// round 8
// speedup vs baseline: 1.2080x; 1.0808x over previous
#include <cuda_runtime.h>
#include <cstdint>

// Problem shape: predicted/target are [B=2, C=26, 96,96,96] fp32.
#define BB 2
#define CC 26
#define NVOX (96*96*96)       // 884736 voxels per (batch, channel)
#define N4   (NVOX/4)         // 221184 float4 per (batch, channel)
#define THREADS 256
#define BLOCKS_X (N4/THREADS) // 864, exact

// Device scratch (zero-initialized at module load; finalize kernel resets them
// after reading, so every call/graph-replay starts from zeros).
__device__ int g_total[BB*CC];
__device__ int g_correct[BB*CC];

__global__ void __launch_bounds__(THREADS)
idr_hist_kernel(const float* __restrict__ pred, const float* __restrict__ targ) {
    __shared__ int s_total[CC];
    __shared__ int s_corr[CC];
    const int tid = threadIdx.x;
    if (tid < CC) { s_total[tid] = 0; s_corr[tid] = 0; }
    __syncthreads();

    const int b = blockIdx.y;
    const size_t i = (size_t)blockIdx.x * THREADS + tid;   // float4 index within channel
    const float4* __restrict__ p = (const float4*)pred + (size_t)b * CC * N4;
    const float4* __restrict__ t = (const float4*)targ + (size_t)b * CC * N4;

    // argmax over channels for predicted (first-max tie-break: strict >)
    float4 pm = p[i];
    int pax = 0, pay = 0, paz = 0, paw = 0;
    #pragma unroll 5
    for (int c = 1; c < CC; c++) {
        float4 v = p[(size_t)c * N4 + i];
        if (v.x > pm.x) { pm.x = v.x; pax = c; }
        if (v.y > pm.y) { pm.y = v.y; pay = c; }
        if (v.z > pm.z) { pm.z = v.z; paz = c; }
        if (v.w > pm.w) { pm.w = v.w; paw = c; }
    }

    // argmax over channels for target
    float4 tm = t[i];
    int tax = 0, tay = 0, taz = 0, taw = 0;
    #pragma unroll 5
    for (int c = 1; c < CC; c++) {
        float4 v = t[(size_t)c * N4 + i];
        if (v.x > tm.x) { tm.x = v.x; tax = c; }
        if (v.y > tm.y) { tm.y = v.y; tay = c; }
        if (v.z > tm.z) { tm.z = v.z; taz = c; }
        if (v.w > tm.w) { tm.w = v.w; taw = c; }
    }

    // block-local histogram by target class; correct = (pred label == target label)
    atomicAdd(&s_total[tax], 1); if (pax == tax) atomicAdd(&s_corr[tax], 1);
    atomicAdd(&s_total[tay], 1); if (pay == tay) atomicAdd(&s_corr[tay], 1);
    atomicAdd(&s_total[taz], 1); if (paz == taz) atomicAdd(&s_corr[taz], 1);
    atomicAdd(&s_total[taw], 1); if (paw == taw) atomicAdd(&s_corr[taw], 1);

    __syncthreads();
    if (tid < CC) {
        if (s_total[tid]) atomicAdd(&g_total[b*CC + tid], s_total[tid]);
        if (s_corr[tid])  atomicAdd(&g_correct[b*CC + tid], s_corr[tid]);
    }
    // NO epilogue: no extra sync, no fence, no ticket. Blocks retire immediately.
}

// Finalize, parallel: 64 threads, one per (batch, class) counter pair so all
// 104 global loads are in flight at once (one memory round-trip instead of
// 104 serial ones). Threads also reset the counters for the next replay.
__global__ void idr_finalize_kernel(float* __restrict__ out) {
    __shared__ float s_rate[BB*CC];
    __shared__ int   s_present[BB*CC];
    const int k = threadIdx.x;

    if (k < BB*CC) {
        const int c = k % CC;
        int tot  = g_total[k];     // all loads issue concurrently across threads
        int corr = g_correct[k];
        int present = (tot > 0) && (c != 0);          // exclude background class 0
        s_present[k] = present;
        s_rate[k] = present ? (float)corr / (float)tot : 0.0f;
        // reset for next call / graph replay
        g_total[k] = 0;
        g_correct[k] = 0;
    }
    __syncthreads();

    if (k == 0) {
        float acc = 0.0f;
        int n_valid = 0;
        #pragma unroll
        for (int bb = 0; bb < BB; bb++) {
            float sum = 0.0f;
            int np = 0;
            #pragma unroll
            for (int c = 1; c < CC; c++) {            // ascending c: same order as ref
                sum += s_rate[bb*CC + c];
                np  += s_present[bb*CC + c];
            }
            if (np > 0) { n_valid++; acc += sum / (float)np; }
        }
        out[0] = (n_valid > 0) ? acc / (float)n_valid : 0.0f;
    }
}

extern "C" void kernel_launch(void* const* d_in, const int* in_sizes, int n_in,
                              void* d_out, int out_size) {
    const float* pred = (const float*)d_in[0];
    const float* targ = (const float*)d_in[1];
    float* out = (float*)d_out;

    dim3 grid(BLOCKS_X, BB);
    idr_hist_kernel<<<grid, THREADS>>>(pred, targ);
    idr_finalize_kernel<<<1, 64>>>(out);
}